// round 3
// baseline (speedup 1.0000x reference)
#include <cuda_runtime.h>
#include <cuda_bf16.h>
#include <cstdint>

// ---------------- problem constants ----------------
#define VOCAB 50000
#define EMB   1024
#define HID   2048
#define BATCH 256
#define SEQ   128
#define NG    6144            // packed gate columns: i(2048) g(2048) o(2048); f-gate unused
#define G4    8192            // 4*HID in original weights

// ---------------- scratch (__device__ globals: no allocation allowed) ----------------
__device__ float g_Xemb[(size_t)BATCH * SEQ * EMB];          // [t*256+b][1024], tf32-rounded
__device__ float g_G[(size_t)BATCH * SEQ * NG];              // precomputed x@W_ih_b^T + biases (fp32)
__device__ float g_Whh[(size_t)NG * HID];                    // packed W_hh_b rows (i,g,o), tf32
__device__ float g_Wib[(size_t)NG * EMB];                    // packed W_ih_b, tf32
__device__ float g_Wif[(size_t)NG * EMB];                    // packed W_ih_f, tf32
__device__ float g_bb[NG];
__device__ float g_bf[NG];
__device__ float g_H[2][(size_t)BATCH * HID];                // h ping-pong, tf32-rounded

// ---------------- helpers ----------------
__device__ __forceinline__ unsigned tf32r_u(float f) {
    unsigned u;
    asm("cvt.rna.tf32.f32 %0, %1;" : "=r"(u) : "f"(f));
    return u;
}
__device__ __forceinline__ float tf32r(float f) { return __uint_as_float(tf32r_u(f)); }

__device__ __forceinline__ void mma_tf32(float d[4], const unsigned a[4], const unsigned b[2]) {
    asm volatile(
        "mma.sync.aligned.m16n8k8.row.col.f32.tf32.tf32.f32 "
        "{%0,%1,%2,%3},{%4,%5,%6,%7},{%8,%9},{%0,%1,%2,%3};\n"
        : "+f"(d[0]), "+f"(d[1]), "+f"(d[2]), "+f"(d[3])
        : "r"(a[0]), "r"(a[1]), "r"(a[2]), "r"(a[3]), "r"(b[0]), "r"(b[1]));
}

#define CP16(saddr, gptr) \
    asm volatile("cp.async.cg.shared.global [%0], [%1], 16;" :: "r"(saddr), "l"(gptr))

// ---------------- gather + tf32 round embeddings ----------------
__global__ void gather_embed(const int* __restrict__ idx, const float* __restrict__ table,
                             float* __restrict__ dst) {
    int m = blockIdx.x;                 // m = t*256 + b
    int t = m >> 8, b = m & 255;
    int row = idx[b * SEQ + t];
    if ((unsigned)row >= (unsigned)VOCAB) row = 0;   // ref: inputs > VOCAB -> 0 (values are <VOCAB)
    const float4* src = (const float4*)(table + (size_t)row * EMB);
    float4 v = src[threadIdx.x];
    uint4 o;
    o.x = tf32r_u(v.x); o.y = tf32r_u(v.y); o.z = tf32r_u(v.z); o.w = tf32r_u(v.w);
    ((uint4*)(dst + (size_t)m * EMB))[threadIdx.x] = o;
}

// ---------------- pack weights: remap rows (i,g,o), tf32 round ----------------
__global__ void pack_weight(float* __restrict__ dst, const float* __restrict__ src, int K) {
    int n = blockIdx.x;                               // 0..6143 packed column
    int wr = n + (n >= 2048 ? 2048 : 0);              // i: rows 0-2047, g: 4096-6143, o: 6144-8191
    const float4* s = (const float4*)(src + (size_t)wr * K);
    float4*       d = (float4*)(dst + (size_t)n * K);
    for (int i = threadIdx.x; i < (K >> 2); i += blockDim.x) {
        float4 v = s[i];
        v.x = tf32r(v.x); v.y = tf32r(v.y); v.z = tf32r(v.z); v.w = tf32r(v.w);
        d[i] = v;
    }
}

__global__ void pack_bias(float* __restrict__ db, const float* __restrict__ bi_b, const float* __restrict__ bh_b,
                          float* __restrict__ df, const float* __restrict__ bi_f, const float* __restrict__ bh_f) {
    int n = blockIdx.x * blockDim.x + threadIdx.x;
    if (n >= NG) return;
    int wr = n + (n >= 2048 ? 2048 : 0);
    db[n] = bi_b[wr] + bh_b[wr];
    df[n] = bi_f[wr] + bh_f[wr];
}

// ---------------- unified GEMM (+optional cell epilogue) ----------------
// C[m][n] = sum_k A[m][k] * Bw[n][k]  over packed columns n in {i,g,o} trio of j-chunk blockIdx.y
// CTA tile: 64 rows x 192 cols (3 panels x 64). 8 warps (2x4), warp tile 32x48.
// mode_cell=0: store gates+bias to out (ld=NG).
// mode_cell=1: gates+addend -> smem -> h = sig(o)*tanh(sig(i)*tanh(g)) -> out (round_h: tf32-round)
#define KC 32
#define SMEM_FLOATS (2*64*36 + 2*192*36)
#define SMEM_BYTES  (SMEM_FLOATS * 4)

__device__ __forceinline__ void cp_issue(const float* __restrict__ A, int lda,
                                         const float* __restrict__ Bw, int K,
                                         int m0, int j0, int tid, int kt,
                                         unsigned sa, unsigned sb) {
#pragma unroll
    for (int i = 0; i < 2; ++i) {
        int slot = tid + i * 256;
        int am = slot >> 3, akq = slot & 7;
        const float* src = A + (size_t)(m0 + am) * lda + kt * KC + akq * 4;
        CP16(sa + (unsigned)(am * 36 + akq * 4) * 4u, src);
    }
#pragma unroll
    for (int i = 0; i < 6; ++i) {
        int slot = tid + i * 256;
        int bn = slot >> 3, bkq = slot & 7;
        int wr = ((bn >> 6) << 11) + j0 + (bn & 63);
        const float* src = Bw + (size_t)wr * K + kt * KC + bkq * 4;
        CP16(sb + (unsigned)(bn * 36 + bkq * 4) * 4u, src);
    }
    asm volatile("cp.async.commit_group;");
}

__global__ __launch_bounds__(256) void lstm_gemm(
    const float* __restrict__ A, int lda, int K,
    const float* __restrict__ Bw,
    const float* __restrict__ addend, int addend_is_matrix,
    float* __restrict__ out, int mode_cell, int round_h, int out_ld)
{
    extern __shared__ float sm[];
    const int tid = threadIdx.x;
    const int lane = tid & 31, warp = tid >> 5;
    const int gid = lane >> 2, tig = lane & 3;
    const int wm = warp >> 2, wn = warp & 3;
    const int m0 = blockIdx.x * 64;
    const int j0 = blockIdx.y * 64;

    float acc[2][6][4];
#pragma unroll
    for (int mt = 0; mt < 2; ++mt)
#pragma unroll
        for (int nt = 0; nt < 6; ++nt)
#pragma unroll
            for (int c = 0; c < 4; ++c) acc[mt][nt][c] = 0.f;

    unsigned sa0 = (unsigned)__cvta_generic_to_shared(sm);
    unsigned sa1 = sa0 + 64 * 36 * 4;
    unsigned sb0 = sa0 + 2 * 64 * 36 * 4;
    unsigned sb1 = sb0 + 192 * 36 * 4;

    const int nkt = K >> 5;
    if (nkt > 0) cp_issue(A, lda, Bw, K, m0, j0, tid, 0, sa0, sb0);

    for (int kt = 0; kt < nkt; ++kt) {
        int cur = kt & 1;
        if (kt + 1 < nkt) {
            cp_issue(A, lda, Bw, K, m0, j0, tid, kt + 1, cur ? sa0 : sa1, cur ? sb0 : sb1);
            asm volatile("cp.async.wait_group 1;");
        } else {
            asm volatile("cp.async.wait_group 0;");
        }
        __syncthreads();

        const unsigned* Asm = (const unsigned*)(sm + cur * 64 * 36);
        const unsigned* Bsm = (const unsigned*)(sm + 2 * 64 * 36 + cur * 192 * 36);

#pragma unroll
        for (int kk = 0; kk < KC; kk += 8) {
            unsigned af[2][4];
#pragma unroll
            for (int mt = 0; mt < 2; ++mt) {
                int rb = wm * 32 + mt * 16;
                af[mt][0] = Asm[(rb + gid)     * 36 + kk + tig];
                af[mt][1] = Asm[(rb + gid + 8) * 36 + kk + tig];
                af[mt][2] = Asm[(rb + gid)     * 36 + kk + tig + 4];
                af[mt][3] = Asm[(rb + gid + 8) * 36 + kk + tig + 4];
            }
            unsigned bf[6][2];
#pragma unroll
            for (int nt = 0; nt < 6; ++nt) {
                int nb = wn * 48 + nt * 8;
                bf[nt][0] = Bsm[(nb + gid) * 36 + kk + tig];
                bf[nt][1] = Bsm[(nb + gid) * 36 + kk + tig + 4];
            }
#pragma unroll
            for (int mt = 0; mt < 2; ++mt)
#pragma unroll
                for (int nt = 0; nt < 6; ++nt)
                    mma_tf32(acc[mt][nt], af[mt], bf[nt]);
        }
        __syncthreads();
    }

    if (!mode_cell) {
        // store raw gates + bias to G (packed column space)
#pragma unroll
        for (int mt = 0; mt < 2; ++mt)
#pragma unroll
            for (int nt = 0; nt < 6; ++nt) {
                int r0 = m0 + wm * 32 + mt * 16 + gid;
                int nloc = wn * 48 + nt * 8 + tig * 2;
                int gcol = ((nloc >> 6) << 11) + j0 + (nloc & 63);
                float b0 = addend[gcol], b1 = addend[gcol + 1];
                float2 v0 = make_float2(acc[mt][nt][0] + b0, acc[mt][nt][1] + b1);
                float2 v1 = make_float2(acc[mt][nt][2] + b0, acc[mt][nt][3] + b1);
                *(float2*)&out[(size_t)r0 * out_ld + gcol] = v0;
                *(float2*)&out[(size_t)(r0 + 8) * out_ld + gcol] = v1;
            }
    } else {
        // stage gates (+addend) into smem trio tile, then apply the cell
        float* Gs = sm;  // [64][193], aliases AB buffers (dead after final sync)
#pragma unroll
        for (int mt = 0; mt < 2; ++mt)
#pragma unroll
            for (int nt = 0; nt < 6; ++nt) {
                int rl = wm * 32 + mt * 16 + gid;
                int nloc = wn * 48 + nt * 8 + tig * 2;
                int gcol = ((nloc >> 6) << 11) + j0 + (nloc & 63);
                float a00, a01, a10, a11;
                if (addend_is_matrix) {
                    const float* p0 = addend + (size_t)(m0 + rl) * NG + gcol;
                    const float* p1 = addend + (size_t)(m0 + rl + 8) * NG + gcol;
                    a00 = p0[0]; a01 = p0[1]; a10 = p1[0]; a11 = p1[1];
                } else {
                    a00 = a10 = addend[gcol];
                    a01 = a11 = addend[gcol + 1];
                }
                Gs[rl * 193 + nloc]           = acc[mt][nt][0] + a00;
                Gs[rl * 193 + nloc + 1]       = acc[mt][nt][1] + a01;
                Gs[(rl + 8) * 193 + nloc]     = acc[mt][nt][2] + a10;
                Gs[(rl + 8) * 193 + nloc + 1] = acc[mt][nt][3] + a11;
            }
        __syncthreads();
#pragma unroll
        for (int e = tid; e < 64 * 64; e += 256) {
            int rl = e >> 6, j = e & 63;
            float gi = Gs[rl * 193 + j];
            float gg = Gs[rl * 193 + 64 + j];
            float go = Gs[rl * 193 + 128 + j];
            float c = (1.f / (1.f + expf(-gi))) * tanhf(gg);
            float h = (1.f / (1.f + expf(-go))) * tanhf(c);
            float* op = out + (size_t)(m0 + rl) * out_ld + j0 + j;
            *op = round_h ? tf32r(h) : h;
        }
    }
}

// ---------------- launch ----------------
extern "C" void kernel_launch(void* const* d_in, const int* in_sizes, int n_in,
                              void* d_out, int out_size) {
    const int*   inputs = (const int*)d_in[0];
    const float* table  = (const float*)d_in[1];
    const float* Wih_f  = (const float*)d_in[2];
    // d_in[3] = W_hh_f: mathematically unused (forward h = 0)
    const float* bih_f  = (const float*)d_in[4];
    const float* bhh_f  = (const float*)d_in[5];
    const float* Wih_b  = (const float*)d_in[6];
    const float* Whh_b  = (const float*)d_in[7];
    const float* bih_b  = (const float*)d_in[8];
    const float* bhh_b  = (const float*)d_in[9];
    float* out = (float*)d_out;

    float *Xemb, *G, *Whh, *Wib, *Wif, *bb, *bf, *H;
    cudaGetSymbolAddress((void**)&Xemb, g_Xemb);
    cudaGetSymbolAddress((void**)&G,    g_G);
    cudaGetSymbolAddress((void**)&Whh,  g_Whh);
    cudaGetSymbolAddress((void**)&Wib,  g_Wib);
    cudaGetSymbolAddress((void**)&Wif,  g_Wif);
    cudaGetSymbolAddress((void**)&bb,   g_bb);
    cudaGetSymbolAddress((void**)&bf,   g_bf);
    cudaGetSymbolAddress((void**)&H,    g_H);

    cudaFuncSetAttribute(lstm_gemm, cudaFuncAttributeMaxDynamicSharedMemorySize, SMEM_BYTES);

    // independent prep (stream-serialized; all cheap)
    gather_embed<<<BATCH * SEQ, 256>>>(inputs, table, Xemb);
    pack_weight<<<NG, 256>>>(Whh, Whh_b, HID);
    pack_weight<<<NG, 256>>>(Wib, Wih_b, EMB);
    pack_weight<<<NG, 256>>>(Wif, Wih_f, EMB);
    pack_bias<<<(NG + 255) / 256, 256>>>(bb, bih_b, bhh_b, bf, bih_f, bhh_f);

    // precompute G[t][b][:] = x @ W_ih_b^T + (b_ih_b + b_hh_b)   (M=32768, N=6144, K=1024)
    lstm_gemm<<<dim3(BATCH * SEQ / 64, 32), 256, SMEM_BYTES>>>(
        Xemb, EMB, EMB, Wib, bb, 0, G, 0, 0, NG);

    // forward direction: single cell on last timestep, h=c=0 -> out[:, 0:2048]
    lstm_gemm<<<dim3(BATCH / 64, 32), 256, SMEM_BYTES>>>(
        Xemb + (size_t)(SEQ - 1) * BATCH * EMB, EMB, EMB, Wif, bf, 0, out, 1, 0, 2 * HID);

    // backward recurrence: 128 steps over reversed sequence
    float* Hb[2] = { H, H + (size_t)BATCH * HID };
    for (int s = 0; s < SEQ; ++s) {
        int t = SEQ - 1 - s;
        const float* Ain = Hb[(s + 1) & 1];           // h from previous step (unused when K=0)
        int Ks = (s == 0) ? 0 : HID;                  // step 0: h=0 -> pure cell on G[127]
        float* op; int oldd; int rf;
        if (s < SEQ - 1) { op = Hb[s & 1]; oldd = HID;     rf = 1; }
        else             { op = out + HID; oldd = 2 * HID; rf = 0; }
        lstm_gemm<<<dim3(BATCH / 64, 32), 256, SMEM_BYTES>>>(
            Ain, HID, Ks, Whh, G + (size_t)t * BATCH * NG, 1, op, 1, rf, oldd);
    }
}

// round 4
// speedup vs baseline: 1.0896x; 1.0896x over previous
#include <cuda_runtime.h>
#include <cuda_bf16.h>
#include <cstdint>

// ---------------- problem constants ----------------
#define VOCAB 50000
#define EMB   1024
#define HID   2048
#define BATCH 256
#define SEQ   128
#define NG    6144            // packed gate cols, interleaved: n = 3*j + gate, gate in {i,g,o}

// ---------------- GEMM tiling ----------------
#define TM 128
#define TN 96
#define KC 32
#define NSTAGE 4
#define SSTR 48                       // smem row stride in floats (32 + 16 pad -> conflict-free LDS.128)
#define ASZ (TM*SSTR)                 // 6144 floats
#define BSZ (TN*SSTR)                 // 4608 floats
#define STG (ASZ+BSZ)                 // 10752 floats per stage
#define SMEM_BYTES (NSTAGE*STG*4)     // 172032 B

// ---------------- scratch (__device__ globals) ----------------
__device__ float g_Xemb[(size_t)BATCH * SEQ * EMB];   // K-permuted, tf32-rounded embeddings
__device__ float g_G[(size_t)BATCH * SEQ * NG];       // precomputed x@W_ih_b^T + biases
__device__ float g_Whh[(size_t)NG * HID];             // packed W_hh_b (interleaved N, permuted K, tf32)
__device__ float g_Wib[(size_t)NG * EMB];
__device__ float g_Wif[(size_t)NG * EMB];
__device__ float g_bb[NG];
__device__ float g_bf[NG];
__device__ float g_H[2][(size_t)BATCH * HID];         // h ping-pong (K-permuted, tf32)

// ---------------- helpers ----------------
__device__ __forceinline__ unsigned tf32r_u(float f) {
    unsigned u;
    asm("cvt.rna.tf32.f32 %0, %1;" : "=r"(u) : "f"(f));
    return u;
}
__device__ __forceinline__ float tf32r(float f) { return __uint_as_float(tf32r_u(f)); }

__device__ __forceinline__ void mma_tf32(float d[4], const unsigned a[4], const unsigned b[2]) {
    asm volatile(
        "mma.sync.aligned.m16n8k8.row.col.f32.tf32.tf32.f32 "
        "{%0,%1,%2,%3},{%4,%5,%6,%7},{%8,%9},{%0,%1,%2,%3};\n"
        : "+f"(d[0]), "+f"(d[1]), "+f"(d[2]), "+f"(d[3])
        : "r"(a[0]), "r"(a[1]), "r"(a[2]), "r"(a[3]), "r"(b[0]), "r"(b[1]));
}

#define CP16(saddr, gptr) \
    asm volatile("cp.async.cg.shared.global [%0], [%1], 16;" :: "r"(saddr), "l"(gptr))

// K-permutation: within each 16-group, position p holds original j = perm16(p),
// perm16(x) = (x&3)*4 + (x>>2)  (involution: 4x4 transpose).
// Thread's float4 at p = tig*4 then holds originals {tig, tig+4, tig+8, tig+12}.

// ---------------- gather + permute + tf32 round embeddings ----------------
__global__ void gather_embed(const int* __restrict__ idx, const float* __restrict__ table,
                             float* __restrict__ dst) {
    int m = blockIdx.x;                 // m = t*256 + b
    int g = threadIdx.x;                // 16-group index, 64 groups per row
    int t = m >> 8, b = m & 255;
    int row = idx[b * SEQ + t];
    if ((unsigned)row >= (unsigned)VOCAB) row = 0;
    const float4* s = (const float4*)(table + (size_t)row * EMB + g * 16);
    float4 s0 = s[0], s1 = s[1], s2 = s[2], s3 = s[3];
    float4* d = (float4*)(dst + (size_t)m * EMB + g * 16);
    d[0] = make_float4(tf32r(s0.x), tf32r(s1.x), tf32r(s2.x), tf32r(s3.x));
    d[1] = make_float4(tf32r(s0.y), tf32r(s1.y), tf32r(s2.y), tf32r(s3.y));
    d[2] = make_float4(tf32r(s0.z), tf32r(s1.z), tf32r(s2.z), tf32r(s3.z));
    d[3] = make_float4(tf32r(s0.w), tf32r(s1.w), tf32r(s2.w), tf32r(s3.w));
}

// ---------------- pack weights: interleave gate rows (n=3j+gate), permute K, tf32 ----------------
__global__ void pack_weight(float* __restrict__ dst, const float* __restrict__ src, int K) {
    int n = blockIdx.x;                               // packed column 0..6143
    int j = n / 3, gate = n - 3 * j;
    int wr = j + (gate == 0 ? 0 : (gate == 1 ? 4096 : 6144));   // i, g, o rows; f unused
    const float4* s = (const float4*)(src + (size_t)wr * K);
    float4*       d = (float4*)(dst + (size_t)n * K);
    for (int g = threadIdx.x; g < (K >> 4); g += blockDim.x) {
        float4 s0 = s[g*4], s1 = s[g*4+1], s2 = s[g*4+2], s3 = s[g*4+3];
        d[g*4+0] = make_float4(tf32r(s0.x), tf32r(s1.x), tf32r(s2.x), tf32r(s3.x));
        d[g*4+1] = make_float4(tf32r(s0.y), tf32r(s1.y), tf32r(s2.y), tf32r(s3.y));
        d[g*4+2] = make_float4(tf32r(s0.z), tf32r(s1.z), tf32r(s2.z), tf32r(s3.z));
        d[g*4+3] = make_float4(tf32r(s0.w), tf32r(s1.w), tf32r(s2.w), tf32r(s3.w));
    }
}

__global__ void pack_bias(float* __restrict__ db, const float* __restrict__ bi_b, const float* __restrict__ bh_b,
                          float* __restrict__ df, const float* __restrict__ bi_f, const float* __restrict__ bh_f) {
    int n = blockIdx.x * blockDim.x + threadIdx.x;
    if (n >= NG) return;
    int j = n / 3, gate = n - 3 * j;
    int wr = j + (gate == 0 ? 0 : (gate == 1 ? 4096 : 6144));
    db[n] = bi_b[wr] + bh_b[wr];
    df[n] = bi_f[wr] + bh_f[wr];
}

// ---------------- unified GEMM (+optional cell epilogue) ----------------
// C[m][n] = sum_k A[m][k]*Bw[n][k], CTA tile 128x96, 8 warps (4x2), warp tile 32x48.
// 4-stage cp.async pipeline, one __syncthreads per k-tile, float4 fragment loads.
// mode_cell=0: out[m][n] = C + addend[n]            (G precompute; out_ld=NG)
// mode_cell=1: gates = C + addend (vec or matrix); h = sig(o)*tanh(sig(i)*tanh(g))
//              round_h=1 -> write tf32(h) at K-permuted col (feeds next step's A)
__global__ __launch_bounds__(256) void lstm_gemm(
    const float* __restrict__ A, int K,
    const float* __restrict__ Bw,
    const float* __restrict__ addend, int addend_is_matrix,
    float* __restrict__ out, int mode_cell, int round_h, int out_ld)
{
    extern __shared__ float sm[];
    const int tid = threadIdx.x;
    const int lane = tid & 31, warp = tid >> 5;
    const int gid = lane >> 2, tig = lane & 3;
    const int wm = warp & 3;          // 4 row bands of 32
    const int wn = warp >> 2;         // 2 col bands of 48
    const int m0 = blockIdx.x * TM;
    const int j0 = blockIdx.y * TN;

    float acc[2][6][4];
#pragma unroll
    for (int mt = 0; mt < 2; ++mt)
#pragma unroll
        for (int nt = 0; nt < 6; ++nt)
#pragma unroll
            for (int c = 0; c < 4; ++c) acc[mt][nt][c] = 0.f;

    unsigned sbase = (unsigned)__cvta_generic_to_shared(sm);
    const int nkt = K >> 5;

    const float* Arow = A + (size_t)m0 * K;
    const float* Brow = Bw + (size_t)j0 * K;

    auto issue = [&](int kt, int stage) {
        unsigned sa = sbase + (unsigned)stage * (STG * 4u);
        unsigned sb = sa + ASZ * 4u;
        const float* Ab = Arow + kt * KC;
        const float* Bb = Brow + kt * KC;
#pragma unroll
        for (int i = 0; i < 4; ++i) {                 // 1024 A chunks
            int s = tid + i * 256;
            int am = s >> 3, q = s & 7;
            CP16(sa + (unsigned)(am * SSTR + q * 4) * 4u, Ab + (size_t)am * K + q * 4);
        }
#pragma unroll
        for (int i = 0; i < 3; ++i) {                 // 768 B chunks
            int s = tid + i * 256;
            int bn = s >> 3, q = s & 7;
            CP16(sb + (unsigned)(bn * SSTR + q * 4) * 4u, Bb + (size_t)bn * K + q * 4);
        }
    };

    if (nkt > 0) {
#pragma unroll
        for (int p = 0; p < 3; ++p) {
            if (p < nkt) issue(p, p);
            asm volatile("cp.async.commit_group;");
        }
        for (int kt = 0; kt < nkt; ++kt) {
            asm volatile("cp.async.wait_group 2;");
            __syncthreads();
            if (kt + 3 < nkt) issue(kt + 3, (kt + 3) & 3);
            asm volatile("cp.async.commit_group;");

            const float4* As = (const float4*)(sm + (kt & 3) * STG);
            const float4* Bs = (const float4*)(sm + (kt & 3) * STG + ASZ);
#pragma unroll
            for (int g16 = 0; g16 < 2; ++g16) {
                float4 a4[2][2];
#pragma unroll
                for (int mt = 0; mt < 2; ++mt) {
                    int r = wm * 32 + mt * 16 + gid;
                    a4[mt][0] = As[r * 12 + g16 * 4 + tig];          // SSTR/4 = 12
                    a4[mt][1] = As[(r + 8) * 12 + g16 * 4 + tig];
                }
                float4 b4[6];
#pragma unroll
                for (int nt = 0; nt < 6; ++nt) {
                    int nb = wn * 48 + nt * 8 + gid;
                    b4[nt] = Bs[nb * 12 + g16 * 4 + tig];
                }
#pragma unroll
                for (int s8 = 0; s8 < 2; ++s8) {
#pragma unroll
                    for (int mt = 0; mt < 2; ++mt) {
                        const unsigned* p0 = (const unsigned*)&a4[mt][0];
                        const unsigned* p1 = (const unsigned*)&a4[mt][1];
                        unsigned a[4] = { p0[2*s8], p1[2*s8], p0[2*s8+1], p1[2*s8+1] };
#pragma unroll
                        for (int nt = 0; nt < 6; ++nt) {
                            const unsigned* pb = (const unsigned*)&b4[nt];
                            unsigned b[2] = { pb[2*s8], pb[2*s8+1] };
                            mma_tf32(acc[mt][nt], a, b);
                        }
                    }
                }
            }
        }
    }

    if (!mode_cell) {
#pragma unroll
        for (int mt = 0; mt < 2; ++mt)
#pragma unroll
            for (int nt = 0; nt < 6; ++nt) {
                int r = m0 + wm * 32 + mt * 16 + gid;
                int n = j0 + wn * 48 + nt * 8 + tig * 2;
                float2 bv = *(const float2*)&addend[n];
                *(float2*)&out[(size_t)r * out_ld + n] =
                    make_float2(acc[mt][nt][0] + bv.x, acc[mt][nt][1] + bv.y);
                *(float2*)&out[(size_t)(r + 8) * out_ld + n] =
                    make_float2(acc[mt][nt][2] + bv.x, acc[mt][nt][3] + bv.y);
            }
    } else {
        __syncthreads();                     // stage buffers are dead; reuse as gate tile
        float* Gs = sm;                      // [128][97]
#pragma unroll
        for (int mt = 0; mt < 2; ++mt)
#pragma unroll
            for (int nt = 0; nt < 6; ++nt) {
                int rl = wm * 32 + mt * 16 + gid;
                int nl = wn * 48 + nt * 8 + tig * 2;
                int n = j0 + nl;
                float a00, a01, a10, a11;
                if (addend_is_matrix) {
                    float2 v0 = *(const float2*)&addend[(size_t)(m0 + rl) * NG + n];
                    float2 v1 = *(const float2*)&addend[(size_t)(m0 + rl + 8) * NG + n];
                    a00 = v0.x; a01 = v0.y; a10 = v1.x; a11 = v1.y;
                } else {
                    float2 bv = *(const float2*)&addend[n];
                    a00 = a10 = bv.x; a01 = a11 = bv.y;
                }
                Gs[rl * 97 + nl]           = acc[mt][nt][0] + a00;
                Gs[rl * 97 + nl + 1]       = acc[mt][nt][1] + a01;
                Gs[(rl + 8) * 97 + nl]     = acc[mt][nt][2] + a10;
                Gs[(rl + 8) * 97 + nl + 1] = acc[mt][nt][3] + a11;
            }
        __syncthreads();
        for (int e = tid; e < TM * 32; e += 256) {
            int row = e >> 5, jj = e & 31;
            float gi = Gs[row * 97 + jj * 3];
            float gg = Gs[row * 97 + jj * 3 + 1];
            float go = Gs[row * 97 + jj * 3 + 2];
            float c = (1.f / (1.f + expf(-gi))) * tanhf(gg);
            float h = (1.f / (1.f + expf(-go))) * tanhf(c);
            int cc = blockIdx.y * 32 + jj;
            if (round_h) {
                int pc = (cc & ~15) | (((cc & 3) << 2) | ((cc >> 2) & 3));   // perm16
                out[(size_t)(m0 + row) * out_ld + pc] = tf32r(h);
            } else {
                out[(size_t)(m0 + row) * out_ld + cc] = h;
            }
        }
    }
}

// ---------------- launch ----------------
extern "C" void kernel_launch(void* const* d_in, const int* in_sizes, int n_in,
                              void* d_out, int out_size) {
    const int*   inputs = (const int*)d_in[0];
    const float* table  = (const float*)d_in[1];
    const float* Wih_f  = (const float*)d_in[2];
    // d_in[3] = W_hh_f: mathematically unused (forward h = 0)
    const float* bih_f  = (const float*)d_in[4];
    const float* bhh_f  = (const float*)d_in[5];
    const float* Wih_b  = (const float*)d_in[6];
    const float* Whh_b  = (const float*)d_in[7];
    const float* bih_b  = (const float*)d_in[8];
    const float* bhh_b  = (const float*)d_in[9];
    float* out = (float*)d_out;

    float *Xemb, *G, *Whh, *Wib, *Wif, *bb, *bf, *H;
    cudaGetSymbolAddress((void**)&Xemb, g_Xemb);
    cudaGetSymbolAddress((void**)&G,    g_G);
    cudaGetSymbolAddress((void**)&Whh,  g_Whh);
    cudaGetSymbolAddress((void**)&Wib,  g_Wib);
    cudaGetSymbolAddress((void**)&Wif,  g_Wif);
    cudaGetSymbolAddress((void**)&bb,   g_bb);
    cudaGetSymbolAddress((void**)&bf,   g_bf);
    cudaGetSymbolAddress((void**)&H,    g_H);

    cudaFuncSetAttribute(lstm_gemm, cudaFuncAttributeMaxDynamicSharedMemorySize, SMEM_BYTES);

    // prep
    gather_embed<<<BATCH * SEQ, 64>>>(inputs, table, Xemb);
    pack_weight<<<NG, 128>>>(Whh, Whh_b, HID);
    pack_weight<<<NG, 128>>>(Wib, Wih_b, EMB);
    pack_weight<<<NG, 128>>>(Wif, Wih_f, EMB);
    pack_bias<<<(NG + 255) / 256, 256>>>(bb, bih_b, bhh_b, bf, bih_f, bhh_f);

    // precompute G = x @ W_ih_b^T + (b_ih_b + b_hh_b)   (M=32768, N=6144, K=1024)
    lstm_gemm<<<dim3(BATCH * SEQ / TM, NG / TN), 256, SMEM_BYTES>>>(
        Xemb, EMB, Wib, bb, 0, G, 0, 0, NG);

    // forward direction: single cell on last timestep, h=c=0 -> out[:, 0:2048]
    lstm_gemm<<<dim3(BATCH / TM, NG / TN), 256, SMEM_BYTES>>>(
        Xemb + (size_t)(SEQ - 1) * BATCH * EMB, EMB, Wif, bf, 0, out, 1, 0, 2 * HID);

    // backward recurrence: 128 steps over reversed sequence
    float* Hb[2] = { H, H + (size_t)BATCH * HID };
    for (int s = 0; s < SEQ; ++s) {
        int t = SEQ - 1 - s;
        const float* Ain = Hb[(s + 1) & 1];
        int Ks = (s == 0) ? 0 : HID;          // step 0: h=0, pure cell on G[t=127]
        float* op; int old; int rf;
        if (s < SEQ - 1) { op = Hb[s & 1]; old = HID;     rf = 1; }
        else             { op = out + HID; old = 2 * HID; rf = 0; }
        lstm_gemm<<<dim3(BATCH / TM, NG / TN), 256, SMEM_BYTES>>>(
            Ain, Ks, Whh, G + (size_t)t * BATCH * NG, 1, op, 1, rf, old);
    }
}

// round 6
// speedup vs baseline: 2.2166x; 2.0344x over previous
#include <cuda_runtime.h>
#include <cuda_fp16.h>
#include <cstdint>

// ---------------- problem constants ----------------
#define VOCAB 50000
#define EMB   1024
#define HID   2048
#define BATCH 256
#define SEQ   128
#define NG    6144            // packed gate cols, interleaved: n = 3*j + gate, gate in {i,g,o}

// ---------------- GEMM tiling ----------------
#define TM 128
#define TN 96
#define KC 64                          // fp16 K per stage = 128B rows (SW128 atom)
#define DEPTH 4
#define STAGE_A (128*128)              // 16384 B
#define STAGE_B (96*128)               // 12288 B
#define STAGE_BYTES (STAGE_A+STAGE_B)  // 28672 B
#define SMEM_BYTES (DEPTH*STAGE_BYTES) // 114688 B

// ---------------- scratch (__device__ globals) ----------------
__device__ __half g_Xemb[(size_t)BATCH * SEQ * EMB];   // fp16 embeddings, K-major
__device__ float  g_G[(size_t)SEQ * NG * BATCH];       // precomputed gates, layout [t][n][b]
__device__ __half g_Whh[(size_t)NG * HID];             // packed fp16 weights (n = 3j+gate)
__device__ __half g_Wib[(size_t)NG * EMB];
__device__ __half g_Wif[(size_t)NG * EMB];
__device__ float  g_bb[NG];
__device__ float  g_bf[NG];
__device__ __half g_H[2][(size_t)BATCH * HID];         // h ping-pong fp16

// ---------------- helpers ----------------
__device__ __forceinline__ uint32_t smem_u32(const void* p) {
    uint32_t a;
    asm("{ .reg .u64 t; cvta.to.shared.u64 t, %1; cvt.u32.u64 %0, t; }" : "=r"(a) : "l"(p));
    return a;
}

#define CP16(saddr, gptr) \
    asm volatile("cp.async.cg.shared.global [%0], [%1], 16;" :: "r"(saddr), "l"(gptr))

#define LDSM4(r, a) \
    asm volatile("ldmatrix.sync.aligned.m8n8.x4.shared.b16 {%0,%1,%2,%3}, [%4];" \
        : "=r"((r)[0]), "=r"((r)[1]), "=r"((r)[2]), "=r"((r)[3]) : "r"(a))

__device__ __forceinline__ void mma_f16(float c[4], const uint32_t a[4],
                                        uint32_t b0, uint32_t b1) {
    asm volatile(
        "mma.sync.aligned.m16n8k16.row.col.f32.f16.f16.f32 "
        "{%0,%1,%2,%3},{%4,%5,%6,%7},{%8,%9},{%0,%1,%2,%3};"
        : "+f"(c[0]), "+f"(c[1]), "+f"(c[2]), "+f"(c[3])
        : "r"(a[0]), "r"(a[1]), "r"(a[2]), "r"(a[3]), "r"(b0), "r"(b1));
}

__device__ __forceinline__ float sigm(float x)  { return 1.f / (1.f + __expf(-x)); }
__device__ __forceinline__ float tanhe(float x) { return 2.f / (1.f + __expf(-2.f * x)) - 1.f; }

// ---------------- prep kernels ----------------
__global__ void gather_embed(const int* __restrict__ idx, const float* __restrict__ table,
                             __half* __restrict__ dst) {
    int m = blockIdx.x;                 // m = t*256 + b
    int t = m >> 8, b = m & 255;
    int row = idx[b * SEQ + t];
    if ((unsigned)row >= (unsigned)VOCAB) row = 0;
    const float4* s = (const float4*)(table + (size_t)row * EMB) + threadIdx.x * 2;
    float4 v0 = s[0], v1 = s[1];
    __half2 h0 = __floats2half2_rn(v0.x, v0.y), h1 = __floats2half2_rn(v0.z, v0.w);
    __half2 h2 = __floats2half2_rn(v1.x, v1.y), h3 = __floats2half2_rn(v1.z, v1.w);
    uint4 o = make_uint4(*(uint32_t*)&h0, *(uint32_t*)&h1, *(uint32_t*)&h2, *(uint32_t*)&h3);
    ((uint4*)(dst + (size_t)m * EMB))[threadIdx.x] = o;
}

__global__ void pack_weight(__half* __restrict__ dst, const float* __restrict__ src, int K) {
    int n = blockIdx.x;                                // packed column 0..6143
    int j = n / 3, gate = n - 3 * j;
    int wr = j + (gate == 0 ? 0 : (gate == 1 ? 4096 : 6144));   // i, g, o rows; f unused
    const float4* s = (const float4*)(src + (size_t)wr * K);
    uint4* d = (uint4*)(dst + (size_t)n * K);
    for (int i = threadIdx.x; i < (K >> 3); i += blockDim.x) {
        float4 a = s[i * 2], b = s[i * 2 + 1];
        __half2 h0 = __floats2half2_rn(a.x, a.y), h1 = __floats2half2_rn(a.z, a.w);
        __half2 h2 = __floats2half2_rn(b.x, b.y), h3 = __floats2half2_rn(b.z, b.w);
        d[i] = make_uint4(*(uint32_t*)&h0, *(uint32_t*)&h1, *(uint32_t*)&h2, *(uint32_t*)&h3);
    }
}

__global__ void pack_bias(float* __restrict__ db, const float* __restrict__ bi_b, const float* __restrict__ bh_b,
                          float* __restrict__ df, const float* __restrict__ bi_f, const float* __restrict__ bh_f) {
    int n = blockIdx.x * blockDim.x + threadIdx.x;
    if (n >= NG) return;
    int j = n / 3, gate = n - 3 * j;
    int wr = j + (gate == 0 ? 0 : (gate == 1 ? 4096 : 6144));
    db[n] = bi_b[wr] + bh_b[wr];
    df[n] = bi_f[wr] + bh_f[wr];
}

// ---------------- fp16 HMMA GEMM + cell ----------------
// C[m][n] = sum_k A[m][k]*W[n][k], fp16 in, fp32 accum. CTA 128x96, 8 warps (4m x 2n),
// warp tile 32x48, KC=64 per stage, SW128 smem + ldmatrix (conflict-free).
// mode 0: outf[t][n][b] = C + addend[n]                (G precompute)
// mode 1: gates = C + addend (vector [n] or matrix [n][256]);
//         h = sig(o)*tanh(sig(i)*tanh(g));
//         round_h=1 -> fp16 h to outh [256][HID]; else fp32 h to outf (ld=out_ld)
__global__ __launch_bounds__(256) void lstm_gemm(
    const __half* __restrict__ A, int K, const __half* __restrict__ W,
    const float* __restrict__ addend, int addmat,
    float* __restrict__ outf, __half* __restrict__ outh,
    int mode, int round_h, int out_ld)
{
    extern __shared__ char smem[];
    const uint32_t sbase = smem_u32(smem);
    const int tid = threadIdx.x;
    const int lane = tid & 31, warp = tid >> 5;
    const int gid = lane >> 2, tig = lane & 3;
    const int wm = warp & 3, wn = warp >> 2;
    const int m0 = blockIdx.x * TM;
    const int j0 = blockIdx.y * TN;

    float acc[2][6][4];
#pragma unroll
    for (int mt = 0; mt < 2; ++mt)
#pragma unroll
        for (int nt = 0; nt < 6; ++nt)
#pragma unroll
            for (int c = 0; c < 4; ++c) acc[mt][nt][c] = 0.f;

    // lane-constant ldmatrix address components (SW128 xor term is lane-constant)
    const int ar = wm * 32 + (lane & 15);
    const uint32_t aoff0 = (uint32_t)ar * 128u;
    const uint32_t aoff1 = aoff0 + 16u * 128u;
    const uint32_t aswz  = (uint32_t)(ar & 7) << 4;
    const uint32_t akh   = ((lane >> 4) & 1) << 4;

    const int brb = wn * 48 + (lane & 7) + ((lane >> 4) << 3);
    const uint32_t bswz = (uint32_t)(brb & 7) << 4;
    const uint32_t bkh  = ((lane >> 3) & 1) << 4;
    const uint32_t boff0 = (uint32_t)brb * 128u;
    const uint32_t boff1 = boff0 + 16u * 128u;
    const uint32_t boff2 = boff0 + 32u * 128u;

    const int nkt = K >> 6;

    if (nkt > 0) {
        const char* Abase = (const char*)A + (size_t)m0 * 2 * K;
        const char* Bbase = (const char*)W + (size_t)j0 * 2 * K;

        auto fill = [&](int kt) {
            uint32_t st = sbase + (uint32_t)(kt & 3) * STAGE_BYTES;
            const char* Ab = Abase + kt * 128;
            const char* Bb = Bbase + kt * 128;
#pragma unroll
            for (int i = 0; i < 4; ++i) {             // A: 1024 x 16B
                int s = tid + i * 256;
                int row = s >> 3, q = s & 7;
                CP16(st + (uint32_t)(row * 128) + (((uint32_t)(q * 16)) ^ ((uint32_t)(row & 7) << 4)),
                     Ab + (size_t)row * 2 * K + q * 16);
            }
            uint32_t stb = st + STAGE_A;
#pragma unroll
            for (int i = 0; i < 3; ++i) {             // B: 768 x 16B
                int s = tid + i * 256;
                int row = s >> 3, q = s & 7;
                CP16(stb + (uint32_t)(row * 128) + (((uint32_t)(q * 16)) ^ ((uint32_t)(row & 7) << 4)),
                     Bb + (size_t)row * 2 * K + q * 16);
            }
        };

#pragma unroll
        for (int p = 0; p < DEPTH - 1; ++p) {
            if (p < nkt) fill(p);
            asm volatile("cp.async.commit_group;");
        }

        for (int kt = 0; kt < nkt; ++kt) {
            asm volatile("cp.async.wait_group %0;" :: "n"(DEPTH - 2));
            __syncthreads();
            if (kt + DEPTH - 1 < nkt) fill(kt + DEPTH - 1);
            asm volatile("cp.async.commit_group;");

            uint32_t st  = sbase + (uint32_t)(kt & 3) * STAGE_BYTES;
            uint32_t stB = st + STAGE_A;
#pragma unroll
            for (int ks = 0; ks < 4; ++ks) {
                uint32_t ca = ((uint32_t)(ks * 32) | akh) ^ aswz;
                uint32_t a0[4], a1[4];
                LDSM4(a0, st + aoff0 + ca);
                LDSM4(a1, st + aoff1 + ca);
                uint32_t cb = ((uint32_t)(ks * 32) | bkh) ^ bswz;
                uint32_t b0[4], b1[4], b2[4];
                LDSM4(b0, stB + boff0 + cb);
                LDSM4(b1, stB + boff1 + cb);
                LDSM4(b2, stB + boff2 + cb);

                mma_f16(acc[0][0], a0, b0[0], b0[1]);  mma_f16(acc[1][0], a1, b0[0], b0[1]);
                mma_f16(acc[0][1], a0, b0[2], b0[3]);  mma_f16(acc[1][1], a1, b0[2], b0[3]);
                mma_f16(acc[0][2], a0, b1[0], b1[1]);  mma_f16(acc[1][2], a1, b1[0], b1[1]);
                mma_f16(acc[0][3], a0, b1[2], b1[3]);  mma_f16(acc[1][3], a1, b1[2], b1[3]);
                mma_f16(acc[0][4], a0, b2[0], b2[1]);  mma_f16(acc[1][4], a1, b2[0], b2[1]);
                mma_f16(acc[0][5], a0, b2[2], b2[3]);  mma_f16(acc[1][5], a1, b2[2], b2[3]);
            }
        }
    }

    // ---------------- epilogue ----------------
    if (mode == 0) {
        // store C + bias to G[t][n][b]; CTA rows never cross a t boundary (TM=128 | 256)
        const int t = m0 >> 8;
        float* Gt = outf + (size_t)t * ((size_t)NG * 256);
#pragma unroll
        for (int mt = 0; mt < 2; ++mt)
#pragma unroll
            for (int nt = 0; nt < 6; ++nt) {
                int b = ((m0 + wm * 32 + mt * 16 + gid) & 255);
                int n = j0 + wn * 48 + nt * 8 + tig * 2;
                float bv0 = addend[n], bv1 = addend[n + 1];
                Gt[(size_t)n * 256 + b]           = acc[mt][nt][0] + bv0;
                Gt[(size_t)(n + 1) * 256 + b]     = acc[mt][nt][1] + bv1;
                Gt[(size_t)n * 256 + b + 8]       = acc[mt][nt][2] + bv0;
                Gt[(size_t)(n + 1) * 256 + b + 8] = acc[mt][nt][3] + bv1;
            }
    } else {
        __syncthreads();                      // stage buffers dead (tail fills are empty groups)
        float* Gs = (float*)smem;             // [128][98]
#pragma unroll
        for (int mt = 0; mt < 2; ++mt)
#pragma unroll
            for (int nt = 0; nt < 6; ++nt) {
                int rl = wm * 32 + mt * 16 + gid;
                int nl = wn * 48 + nt * 8 + tig * 2;
                int n = j0 + nl;
                float a00, a01, a10, a11;
                if (addmat) {
                    const float* c0 = addend + (size_t)n * 256 + m0 + rl;
                    const float* c1 = addend + (size_t)(n + 1) * 256 + m0 + rl;
                    a00 = c0[0]; a10 = c0[8];
                    a01 = c1[0]; a11 = c1[8];
                } else {
                    a00 = a10 = addend[n];
                    a01 = a11 = addend[n + 1];
                }
                Gs[rl * 98 + nl]           = acc[mt][nt][0] + a00;
                Gs[rl * 98 + nl + 1]       = acc[mt][nt][1] + a01;
                Gs[(rl + 8) * 98 + nl]     = acc[mt][nt][2] + a10;
                Gs[(rl + 8) * 98 + nl + 1] = acc[mt][nt][3] + a11;
            }
        __syncthreads();
        for (int e = tid; e < TM * 32; e += 256) {
            int row = e >> 5, jl = e & 31;
            float gi = Gs[row * 98 + jl * 3];
            float gg = Gs[row * 98 + jl * 3 + 1];
            float go = Gs[row * 98 + jl * 3 + 2];
            float cc = sigm(gi) * tanhe(gg);
            float h  = sigm(go) * tanhe(cc);
            int j = blockIdx.y * 32 + jl;
            if (round_h) outh[(size_t)(m0 + row) * HID + j] = __float2half(h);
            else         outf[(size_t)(m0 + row) * out_ld + j] = h;
        }
    }
}

// ---------------- launch ----------------
extern "C" void kernel_launch(void* const* d_in, const int* in_sizes, int n_in,
                              void* d_out, int out_size) {
    const int*   inputs = (const int*)d_in[0];
    const float* table  = (const float*)d_in[1];
    const float* Wih_f  = (const float*)d_in[2];
    // d_in[3] = W_hh_f: mathematically unused (forward h = 0)
    const float* bih_f  = (const float*)d_in[4];
    const float* bhh_f  = (const float*)d_in[5];
    const float* Wih_b  = (const float*)d_in[6];
    const float* Whh_b  = (const float*)d_in[7];
    const float* bih_b  = (const float*)d_in[8];
    const float* bhh_b  = (const float*)d_in[9];
    float* out = (float*)d_out;

    __half *Xemb, *Whh, *Wib, *Wif, *H;
    float *G, *bb, *bf;
    cudaGetSymbolAddress((void**)&Xemb, g_Xemb);
    cudaGetSymbolAddress((void**)&G,    g_G);
    cudaGetSymbolAddress((void**)&Whh,  g_Whh);
    cudaGetSymbolAddress((void**)&Wib,  g_Wib);
    cudaGetSymbolAddress((void**)&Wif,  g_Wif);
    cudaGetSymbolAddress((void**)&bb,   g_bb);
    cudaGetSymbolAddress((void**)&bf,   g_bf);
    cudaGetSymbolAddress((void**)&H,    g_H);

    cudaFuncSetAttribute(lstm_gemm, cudaFuncAttributeMaxDynamicSharedMemorySize, SMEM_BYTES);

    // prep
    gather_embed<<<BATCH * SEQ, 128>>>(inputs, table, Xemb);
    pack_weight<<<NG, 128>>>(Whh, Whh_b, HID);
    pack_weight<<<NG, 128>>>(Wib, Wih_b, EMB);
    pack_weight<<<NG, 128>>>(Wif, Wih_f, EMB);
    pack_bias<<<(NG + 255) / 256, 256>>>(bb, bih_b, bhh_b, bf, bih_f, bhh_f);

    // precompute G[t][n][b] = (x @ W_ih_b^T)[tb][n] + bias  (M=32768, N=6144, K=1024)
    lstm_gemm<<<dim3(BATCH * SEQ / TM, NG / TN), 256, SMEM_BYTES>>>(
        Xemb, EMB, Wib, bb, 0, G, nullptr, 0, 0, 0);

    // forward direction: single cell on last timestep, h=c=0 -> out[:, 0:2048]
    lstm_gemm<<<dim3(BATCH / TM, NG / TN), 256, SMEM_BYTES>>>(
        Xemb + (size_t)(SEQ - 1) * BATCH * EMB, EMB, Wif, bf, 0, out, nullptr, 1, 0, 2 * HID);

    // backward recurrence: 128 steps over reversed sequence
    __half* Hb[2] = { H, H + (size_t)BATCH * HID };
    for (int s = 0; s < SEQ; ++s) {
        int t = SEQ - 1 - s;
        const __half* Ain = Hb[(s + 1) & 1];
        int Ks = (s == 0) ? 0 : HID;          // step 0: h=0, pure cell on G[t=127]
        const float* add = G + (size_t)t * ((size_t)NG * 256);
        if (s < SEQ - 1) {
            lstm_gemm<<<dim3(BATCH / TM, NG / TN), 256, SMEM_BYTES>>>(
                Ain, Ks, Whh, add, 1, nullptr, Hb[s & 1], 1, 1, 0);
        } else {
            lstm_gemm<<<dim3(BATCH / TM, NG / TN), 256, SMEM_BYTES>>>(
                Ain, Ks, Whh, add, 1, out + HID, nullptr, 1, 0, 2 * HID);
        }
    }
}

// round 7
// speedup vs baseline: 2.4916x; 1.1240x over previous
#include <cuda_runtime.h>
#include <cuda_fp16.h>
#include <cstdint>

// ---------------- problem constants ----------------
#define VOCAB 50000
#define EMB   1024
#define HID   2048
#define BATCH 256
#define SEQ   128
#define NG    6144            // packed gate cols, interleaved: n = 3*j + gate, gate in {i,g,o}

// ---------------- GEMM tiling ----------------
#define TM 128
#define TN 96
#define DEPTH 4
#define STAGE_A (128*128)              // 16384 B
#define STAGE_B (96*128)               // 12288 B
#define STAGE_BYTES (STAGE_A+STAGE_B)  // 28672 B
#define GEMM_SMEM (DEPTH*STAGE_BYTES)  // 114688 B
#define GTILE_PITCH_B 272              // 128 halfs (256B) + 16B pad  -> conflict-free
#define GTILE_BYTES (96*GTILE_PITCH_B) // 26112 B
#define RECUR_SMEM (GEMM_SMEM + GTILE_BYTES)   // 140800 B

// ---------------- scratch (__device__ globals) ----------------
__device__ __half g_Xemb[(size_t)BATCH * SEQ * EMB];   // fp16 embeddings, K-major
__device__ __half g_G[(size_t)SEQ * NG * BATCH];       // precomputed gates fp16, layout [t][n][b]
__device__ __half g_Whh[(size_t)NG * HID];             // packed fp16 weights (n = 3j+gate)
__device__ __half g_Wib[(size_t)NG * EMB];
__device__ __half g_Wif[(size_t)NG * EMB];
__device__ float  g_bb[NG];
__device__ float  g_bf[NG];
__device__ __half g_H[2][(size_t)BATCH * HID];         // h ping-pong fp16
__device__ int    g_cnt[2][SEQ];                       // per-x-group step arrival counters

// ---------------- helpers ----------------
__device__ __forceinline__ uint32_t smem_u32(const void* p) {
    uint32_t a;
    asm("{ .reg .u64 t; cvta.to.shared.u64 t, %1; cvt.u32.u64 %0, t; }" : "=r"(a) : "l"(p));
    return a;
}

#define CP16(saddr, gptr) \
    asm volatile("cp.async.cg.shared.global [%0], [%1], 16;" :: "r"(saddr), "l"(gptr))

#define LDSM4(r, a) \
    asm volatile("ldmatrix.sync.aligned.m8n8.x4.shared.b16 {%0,%1,%2,%3}, [%4];" \
        : "=r"((r)[0]), "=r"((r)[1]), "=r"((r)[2]), "=r"((r)[3]) : "r"(a))

__device__ __forceinline__ void mma_f16(float c[4], const uint32_t a[4],
                                        uint32_t b0, uint32_t b1) {
    asm volatile(
        "mma.sync.aligned.m16n8k16.row.col.f32.f16.f16.f32 "
        "{%0,%1,%2,%3},{%4,%5,%6,%7},{%8,%9},{%0,%1,%2,%3};"
        : "+f"(c[0]), "+f"(c[1]), "+f"(c[2]), "+f"(c[3])
        : "r"(a[0]), "r"(a[1]), "r"(a[2]), "r"(a[3]), "r"(b0), "r"(b1));
}

__device__ __forceinline__ float sigm(float x)  { return 1.f / (1.f + __expf(-x)); }
__device__ __forceinline__ float tanhe(float x) { return 2.f / (1.f + __expf(-2.f * x)) - 1.f; }

// ---------------- prep kernels ----------------
__global__ void gather_embed(const int* __restrict__ idx, const float* __restrict__ table,
                             __half* __restrict__ dst) {
    int m = blockIdx.x;                 // m = t*256 + b
    int t = m >> 8, b = m & 255;
    int row = idx[b * SEQ + t];
    if ((unsigned)row >= (unsigned)VOCAB) row = 0;
    const float4* s = (const float4*)(table + (size_t)row * EMB) + threadIdx.x * 2;
    float4 v0 = s[0], v1 = s[1];
    __half2 h0 = __floats2half2_rn(v0.x, v0.y), h1 = __floats2half2_rn(v0.z, v0.w);
    __half2 h2 = __floats2half2_rn(v1.x, v1.y), h3 = __floats2half2_rn(v1.z, v1.w);
    uint4 o = make_uint4(*(uint32_t*)&h0, *(uint32_t*)&h1, *(uint32_t*)&h2, *(uint32_t*)&h3);
    ((uint4*)(dst + (size_t)m * EMB))[threadIdx.x] = o;
}

__global__ void pack_weight(__half* __restrict__ dst, const float* __restrict__ src, int K) {
    int n = blockIdx.x;                                // packed column 0..6143
    int j = n / 3, gate = n - 3 * j;
    int wr = j + (gate == 0 ? 0 : (gate == 1 ? 4096 : 6144));   // i, g, o rows; f unused
    const float4* s = (const float4*)(src + (size_t)wr * K);
    uint4* d = (uint4*)(dst + (size_t)n * K);
    for (int i = threadIdx.x; i < (K >> 3); i += blockDim.x) {
        float4 a = s[i * 2], b = s[i * 2 + 1];
        __half2 h0 = __floats2half2_rn(a.x, a.y), h1 = __floats2half2_rn(a.z, a.w);
        __half2 h2 = __floats2half2_rn(b.x, b.y), h3 = __floats2half2_rn(b.z, b.w);
        d[i] = make_uint4(*(uint32_t*)&h0, *(uint32_t*)&h1, *(uint32_t*)&h2, *(uint32_t*)&h3);
    }
}

__global__ void pack_bias(float* __restrict__ db, const float* __restrict__ bi_b, const float* __restrict__ bh_b,
                          float* __restrict__ df, const float* __restrict__ bi_f, const float* __restrict__ bh_f) {
    int n = blockIdx.x * blockDim.x + threadIdx.x;
    if (n >= NG) return;
    int j = n / 3, gate = n - 3 * j;
    int wr = j + (gate == 0 ? 0 : (gate == 1 ? 4096 : 6144));
    db[n] = bi_b[wr] + bh_b[wr];
    df[n] = bi_f[wr] + bh_f[wr];
}

__global__ void reset_cnt() {
    if (threadIdx.x < 2 * SEQ) ((int*)g_cnt)[threadIdx.x] = 0;
}

// ---------------- one-shot GEMM (precompute / forward cell) ----------------
// mode 0: grid (n-panels, m-panels) so a wave shares the A tile (DRAM-friendly);
//         writes fp16 G[t][n][b] = C + bias[n].
// mode 1: grid (m-panels, n-panels); gates = C + bias; h = sig(o)*tanh(sig(i)*tanh(g));
//         fp32 h to fout (ld = out_ld).
__global__ __launch_bounds__(256) void lstm_gemm(
    const __half* __restrict__ A, int K, const __half* __restrict__ W,
    const float* __restrict__ bias,
    __half* __restrict__ gout, float* __restrict__ fout,
    int mode, int out_ld)
{
    extern __shared__ char smem[];
    const uint32_t sbase = smem_u32(smem);
    const int tid = threadIdx.x;
    const int lane = tid & 31, warp = tid >> 5;
    const int gid = lane >> 2, tig = lane & 3;
    const int wm = warp & 3, wn = warp >> 2;
    const int bm = (mode == 0) ? blockIdx.y : blockIdx.x;
    const int bn = (mode == 0) ? blockIdx.x : blockIdx.y;
    const int m0 = bm * TM;
    const int j0 = bn * TN;

    float acc[2][6][4];
#pragma unroll
    for (int mt = 0; mt < 2; ++mt)
#pragma unroll
        for (int nt = 0; nt < 6; ++nt)
#pragma unroll
            for (int c = 0; c < 4; ++c) acc[mt][nt][c] = 0.f;

    const int ar = wm * 32 + (lane & 15);
    const uint32_t aoff0 = (uint32_t)ar * 128u, aoff1 = aoff0 + 2048u;
    const uint32_t aswz  = (uint32_t)(ar & 7) << 4;
    const uint32_t akh   = ((lane >> 4) & 1) << 4;
    const int brb = wn * 48 + (lane & 7) + ((lane >> 4) << 3);
    const uint32_t bswz = (uint32_t)(brb & 7) << 4;
    const uint32_t bkh  = ((lane >> 3) & 1) << 4;
    const uint32_t boff0 = (uint32_t)brb * 128u, boff1 = boff0 + 2048u, boff2 = boff0 + 4096u;

    const int nkt = K >> 6;
    const char* Abase = (const char*)A + (size_t)m0 * 2 * K;
    const char* Bbase = (const char*)W + (size_t)j0 * 2 * K;

    auto fill = [&](int kt) {
        uint32_t st = sbase + (uint32_t)(kt & 3) * STAGE_BYTES;
        const char* Ab = Abase + kt * 128;
        const char* Bb = Bbase + kt * 128;
#pragma unroll
        for (int i = 0; i < 4; ++i) {
            int s = tid + i * 256;
            int row = s >> 3, q = s & 7;
            CP16(st + (uint32_t)(row * 128) + (((uint32_t)(q * 16)) ^ ((uint32_t)(row & 7) << 4)),
                 Ab + (size_t)row * 2 * K + q * 16);
        }
        uint32_t stb = st + STAGE_A;
#pragma unroll
        for (int i = 0; i < 3; ++i) {
            int s = tid + i * 256;
            int row = s >> 3, q = s & 7;
            CP16(stb + (uint32_t)(row * 128) + (((uint32_t)(q * 16)) ^ ((uint32_t)(row & 7) << 4)),
                 Bb + (size_t)row * 2 * K + q * 16);
        }
    };

#pragma unroll
    for (int p = 0; p < DEPTH - 1; ++p) {
        if (p < nkt) fill(p);
        asm volatile("cp.async.commit_group;");
    }

#pragma unroll 1
    for (int kt = 0; kt < nkt; ++kt) {
        asm volatile("cp.async.wait_group %0;" :: "n"(DEPTH - 2));
        __syncthreads();
        if (kt + DEPTH - 1 < nkt) fill(kt + DEPTH - 1);
        asm volatile("cp.async.commit_group;");

        uint32_t st  = sbase + (uint32_t)(kt & 3) * STAGE_BYTES;
        uint32_t stB = st + STAGE_A;
#pragma unroll
        for (int ks = 0; ks < 4; ++ks) {
            uint32_t ca = ((uint32_t)(ks * 32) | akh) ^ aswz;
            uint32_t a0[4], a1[4];
            LDSM4(a0, st + aoff0 + ca);
            LDSM4(a1, st + aoff1 + ca);
            uint32_t cb = ((uint32_t)(ks * 32) | bkh) ^ bswz;
            uint32_t b0[4], b1[4], b2[4];
            LDSM4(b0, stB + boff0 + cb);
            LDSM4(b1, stB + boff1 + cb);
            LDSM4(b2, stB + boff2 + cb);

            mma_f16(acc[0][0], a0, b0[0], b0[1]);  mma_f16(acc[1][0], a1, b0[0], b0[1]);
            mma_f16(acc[0][1], a0, b0[2], b0[3]);  mma_f16(acc[1][1], a1, b0[2], b0[3]);
            mma_f16(acc[0][2], a0, b1[0], b1[1]);  mma_f16(acc[1][2], a1, b1[0], b1[1]);
            mma_f16(acc[0][3], a0, b1[2], b1[3]);  mma_f16(acc[1][3], a1, b1[2], b1[3]);
            mma_f16(acc[0][4], a0, b2[0], b2[1]);  mma_f16(acc[1][4], a1, b2[0], b2[1]);
            mma_f16(acc[0][5], a0, b2[2], b2[3]);  mma_f16(acc[1][5], a1, b2[2], b2[3]);
        }
    }

    if (mode == 0) {
        const int t = m0 >> 8;
        __half* Gt = gout + (size_t)t * ((size_t)NG * 256);
#pragma unroll
        for (int mt = 0; mt < 2; ++mt)
#pragma unroll
            for (int nt = 0; nt < 6; ++nt) {
                int b = (m0 + wm * 32 + mt * 16 + gid) & 255;
                int n = j0 + wn * 48 + nt * 8 + tig * 2;
                float bv0 = bias[n], bv1 = bias[n + 1];
                Gt[(size_t)n * 256 + b]           = __float2half(acc[mt][nt][0] + bv0);
                Gt[(size_t)(n + 1) * 256 + b]     = __float2half(acc[mt][nt][1] + bv1);
                Gt[(size_t)n * 256 + b + 8]       = __float2half(acc[mt][nt][2] + bv0);
                Gt[(size_t)(n + 1) * 256 + b + 8] = __float2half(acc[mt][nt][3] + bv1);
            }
    } else {
        __syncthreads();
        float* Gs = (float*)smem;             // [128][98]
#pragma unroll
        for (int mt = 0; mt < 2; ++mt)
#pragma unroll
            for (int nt = 0; nt < 6; ++nt) {
                int rl = wm * 32 + mt * 16 + gid;
                int nl = wn * 48 + nt * 8 + tig * 2;
                int n = j0 + nl;
                float a0v = bias[n], a1v = bias[n + 1];
                Gs[rl * 98 + nl]           = acc[mt][nt][0] + a0v;
                Gs[rl * 98 + nl + 1]       = acc[mt][nt][1] + a1v;
                Gs[(rl + 8) * 98 + nl]     = acc[mt][nt][2] + a0v;
                Gs[(rl + 8) * 98 + nl + 1] = acc[mt][nt][3] + a1v;
            }
        __syncthreads();
        for (int e = tid; e < TM * 32; e += 256) {
            int row = e >> 5, jl = e & 31;
            float gi = Gs[row * 98 + jl * 3];
            float gg = Gs[row * 98 + jl * 3 + 1];
            float go = Gs[row * 98 + jl * 3 + 2];
            float cc = sigm(gi) * tanhe(gg);
            float h  = sigm(go) * tanhe(cc);
            fout[(size_t)(m0 + row) * out_ld + bn * 32 + jl] = h;
        }
    }
}

// ---------------- persistent recurrence kernel ----------------
// 128 CTAs (grid 2x64), all resident (1 CTA/SM). Per step s (t = 127-s):
// pre-barrier: cp.async prefetch of G[t] tile (smem) + first 3 W_hh stages;
// flag barrier on own x-group (64 CTAs); then A(=h) pipeline + 32 k-tiles HMMA;
// epilogue: gates = acc + G, cell, h -> H ping-pong fp16 (final step: fp32 out).
__global__ __launch_bounds__(256, 1) void lstm_recur(
    const __half* __restrict__ Gall, const __half* __restrict__ W,
    __half* __restrict__ H0, __half* __restrict__ H1, float* __restrict__ out)
{
    extern __shared__ char smem[];
    const uint32_t sbase = smem_u32(smem);
    const uint32_t gsm = sbase + GEMM_SMEM;
    __half* GsmH = (__half*)(smem + GEMM_SMEM);
    const int tid = threadIdx.x;
    const int lane = tid & 31, warp = tid >> 5;
    const int gid = lane >> 2, tig = lane & 3;
    const int wm = warp & 3, wn = warp >> 2;
    const int x = blockIdx.x, y = blockIdx.y;
    const int m0 = x * TM, j0 = y * TN;
    volatile int* cnt = (volatile int*)&g_cnt[x][0];

    const int ar = wm * 32 + (lane & 15);
    const uint32_t aoff0 = (uint32_t)ar * 128u, aoff1 = aoff0 + 2048u;
    const uint32_t aswz  = (uint32_t)(ar & 7) << 4;
    const uint32_t akh   = ((lane >> 4) & 1) << 4;
    const int brb = wn * 48 + (lane & 7) + ((lane >> 4) << 3);
    const uint32_t bswz = (uint32_t)(brb & 7) << 4;
    const uint32_t bkh  = ((lane >> 3) & 1) << 4;
    const uint32_t boff0 = (uint32_t)brb * 128u, boff1 = boff0 + 2048u, boff2 = boff0 + 4096u;

    const char* Bbase = (const char*)W + (size_t)j0 * 2 * HID;

#pragma unroll 1
    for (int s = 0; s < SEQ; ++s) {
        const int t = (SEQ - 1) - s;

        // --- pre-barrier prefetch: G tile + W stages 0..2 (h-independent) ---
        {
            const char* Gt = (const char*)(Gall + ((size_t)t * NG + j0) * 256 + m0);
#pragma unroll
            for (int i = 0; i < 6; ++i) {                 // 96 rows x 256B = 1536 chunks
                int sl = tid + i * 256;
                int r = sl >> 4, q = sl & 15;
                CP16(gsm + (uint32_t)(r * GTILE_PITCH_B + q * 16), Gt + (size_t)r * 512 + q * 16);
            }
        }
        if (s > 0) {
#pragma unroll
            for (int st_ = 0; st_ < 3; ++st_) {
                uint32_t sb = sbase + (uint32_t)st_ * STAGE_BYTES + STAGE_A;
                const char* Bb = Bbase + st_ * 128;
#pragma unroll
                for (int i = 0; i < 3; ++i) {
                    int sl = tid + i * 256;
                    int row = sl >> 3, q = sl & 7;
                    CP16(sb + (uint32_t)(row * 128) + (((uint32_t)(q * 16)) ^ ((uint32_t)(row & 7) << 4)),
                         Bb + (size_t)row * 2 * HID + q * 16);
                }
            }
        }
        asm volatile("cp.async.commit_group;");

        float acc[2][6][4];
#pragma unroll
        for (int mt = 0; mt < 2; ++mt)
#pragma unroll
            for (int nt = 0; nt < 6; ++nt)
#pragma unroll
                for (int c = 0; c < 4; ++c) acc[mt][nt][c] = 0.f;

        if (s > 0) {
            const __half* Ap = ((s + 1) & 1) ? H1 : H0;   // h from step s-1
            if (tid == 0) {
                while (cnt[s - 1] < 64) { }
                __threadfence();
            }
            __syncthreads();

            const char* Abase = (const char*)Ap + (size_t)m0 * 2 * HID;
#pragma unroll
            for (int st_ = 0; st_ < 3; ++st_) {           // A prologue stages 0..2
                uint32_t sa = sbase + (uint32_t)st_ * STAGE_BYTES;
                const char* Ab = Abase + st_ * 128;
#pragma unroll
                for (int i = 0; i < 4; ++i) {
                    int sl = tid + i * 256;
                    int row = sl >> 3, q = sl & 7;
                    CP16(sa + (uint32_t)(row * 128) + (((uint32_t)(q * 16)) ^ ((uint32_t)(row & 7) << 4)),
                         Ab + (size_t)row * 2 * HID + q * 16);
                }
                asm volatile("cp.async.commit_group;");
            }

#pragma unroll 1
            for (int kt = 0; kt < 32; ++kt) {
                asm volatile("cp.async.wait_group 2;");
                __syncthreads();
                if (kt + 3 < 32) {
                    int kf = kt + 3;
                    uint32_t sa = sbase + (uint32_t)(kf & 3) * STAGE_BYTES;
                    const char* Ab = Abase + kf * 128;
                    const char* Bb = Bbase + kf * 128;
#pragma unroll
                    for (int i = 0; i < 4; ++i) {
                        int sl = tid + i * 256;
                        int row = sl >> 3, q = sl & 7;
                        CP16(sa + (uint32_t)(row * 128) + (((uint32_t)(q * 16)) ^ ((uint32_t)(row & 7) << 4)),
                             Ab + (size_t)row * 2 * HID + q * 16);
                    }
                    uint32_t sb = sa + STAGE_A;
#pragma unroll
                    for (int i = 0; i < 3; ++i) {
                        int sl = tid + i * 256;
                        int row = sl >> 3, q = sl & 7;
                        CP16(sb + (uint32_t)(row * 128) + (((uint32_t)(q * 16)) ^ ((uint32_t)(row & 7) << 4)),
                             Bb + (size_t)row * 2 * HID + q * 16);
                    }
                }
                asm volatile("cp.async.commit_group;");

                uint32_t st  = sbase + (uint32_t)(kt & 3) * STAGE_BYTES;
                uint32_t stB = st + STAGE_A;
#pragma unroll
                for (int ks = 0; ks < 4; ++ks) {
                    uint32_t ca = ((uint32_t)(ks * 32) | akh) ^ aswz;
                    uint32_t a0[4], a1[4];
                    LDSM4(a0, st + aoff0 + ca);
                    LDSM4(a1, st + aoff1 + ca);
                    uint32_t cb = ((uint32_t)(ks * 32) | bkh) ^ bswz;
                    uint32_t b0[4], b1[4], b2[4];
                    LDSM4(b0, stB + boff0 + cb);
                    LDSM4(b1, stB + boff1 + cb);
                    LDSM4(b2, stB + boff2 + cb);

                    mma_f16(acc[0][0], a0, b0[0], b0[1]);  mma_f16(acc[1][0], a1, b0[0], b0[1]);
                    mma_f16(acc[0][1], a0, b0[2], b0[3]);  mma_f16(acc[1][1], a1, b0[2], b0[3]);
                    mma_f16(acc[0][2], a0, b1[0], b1[1]);  mma_f16(acc[1][2], a1, b1[0], b1[1]);
                    mma_f16(acc[0][3], a0, b1[2], b1[3]);  mma_f16(acc[1][3], a1, b1[2], b1[3]);
                    mma_f16(acc[0][4], a0, b2[0], b2[1]);  mma_f16(acc[1][4], a1, b2[0], b2[1]);
                    mma_f16(acc[0][5], a0, b2[2], b2[3]);  mma_f16(acc[1][5], a1, b2[2], b2[3]);
                }
            }
        } else {
            asm volatile("cp.async.wait_group 0;");       // G tile ready
            __syncthreads();
        }

        // ---- epilogue: stage gates (acc + G) into smem, apply cell ----
        float* Gs = (float*)smem;            // [128][98]; stage slots 0-1 are dead here
#pragma unroll
        for (int mt = 0; mt < 2; ++mt)
#pragma unroll
            for (int nt = 0; nt < 6; ++nt) {
                int rl = wm * 32 + mt * 16 + gid;
                int nl = wn * 48 + nt * 8 + tig * 2;
                float a00 = __half2float(GsmH[nl * 136 + rl]);
                float a01 = __half2float(GsmH[(nl + 1) * 136 + rl]);
                float a10 = __half2float(GsmH[nl * 136 + rl + 8]);
                float a11 = __half2float(GsmH[(nl + 1) * 136 + rl + 8]);
                Gs[rl * 98 + nl]           = acc[mt][nt][0] + a00;
                Gs[rl * 98 + nl + 1]       = acc[mt][nt][1] + a01;
                Gs[(rl + 8) * 98 + nl]     = acc[mt][nt][2] + a10;
                Gs[(rl + 8) * 98 + nl + 1] = acc[mt][nt][3] + a11;
            }
        __syncthreads();

        if (s < SEQ - 1) {
            __half* Hout = (s & 1) ? H1 : H0;
            for (int e = tid; e < TM * 32; e += 256) {
                int row = e >> 5, jl = e & 31;
                float gi = Gs[row * 98 + jl * 3];
                float gg = Gs[row * 98 + jl * 3 + 1];
                float go = Gs[row * 98 + jl * 3 + 2];
                float cc = sigm(gi) * tanhe(gg);
                float h  = sigm(go) * tanhe(cc);
                Hout[(size_t)(m0 + row) * HID + y * 32 + jl] = __float2half(h);
            }
        } else {
            for (int e = tid; e < TM * 32; e += 256) {
                int row = e >> 5, jl = e & 31;
                float gi = Gs[row * 98 + jl * 3];
                float gg = Gs[row * 98 + jl * 3 + 1];
                float go = Gs[row * 98 + jl * 3 + 2];
                float cc = sigm(gi) * tanhe(gg);
                float h  = sigm(go) * tanhe(cc);
                out[(size_t)(m0 + row) * (2 * HID) + HID + y * 32 + jl] = h;
            }
        }
        __syncthreads();                     // all reads of Gs/GsmH done before next prefetch
        if (tid == 0 && s < SEQ - 1) {
            __threadfence();
            atomicAdd(&g_cnt[x][s], 1);
        }
    }
}

// ---------------- launch ----------------
extern "C" void kernel_launch(void* const* d_in, const int* in_sizes, int n_in,
                              void* d_out, int out_size) {
    const int*   inputs = (const int*)d_in[0];
    const float* table  = (const float*)d_in[1];
    const float* Wih_f  = (const float*)d_in[2];
    // d_in[3] = W_hh_f: mathematically unused (forward h = 0)
    const float* bih_f  = (const float*)d_in[4];
    const float* bhh_f  = (const float*)d_in[5];
    const float* Wih_b  = (const float*)d_in[6];
    const float* Whh_b  = (const float*)d_in[7];
    const float* bih_b  = (const float*)d_in[8];
    const float* bhh_b  = (const float*)d_in[9];
    float* out = (float*)d_out;

    __half *Xemb, *G, *Whh, *Wib, *Wif, *H;
    float *bb, *bf;
    cudaGetSymbolAddress((void**)&Xemb, g_Xemb);
    cudaGetSymbolAddress((void**)&G,    g_G);
    cudaGetSymbolAddress((void**)&Whh,  g_Whh);
    cudaGetSymbolAddress((void**)&Wib,  g_Wib);
    cudaGetSymbolAddress((void**)&Wif,  g_Wif);
    cudaGetSymbolAddress((void**)&bb,   g_bb);
    cudaGetSymbolAddress((void**)&bf,   g_bf);
    cudaGetSymbolAddress((void**)&H,    g_H);

    cudaFuncSetAttribute(lstm_gemm,  cudaFuncAttributeMaxDynamicSharedMemorySize, GEMM_SMEM);
    cudaFuncSetAttribute(lstm_recur, cudaFuncAttributeMaxDynamicSharedMemorySize, RECUR_SMEM);

    // prep
    gather_embed<<<BATCH * SEQ, 128>>>(inputs, table, Xemb);
    pack_weight<<<NG, 128>>>(Whh, Whh_b, HID);
    pack_weight<<<NG, 128>>>(Wib, Wih_b, EMB);
    pack_weight<<<NG, 128>>>(Wif, Wih_f, EMB);
    pack_bias<<<(NG + 255) / 256, 256>>>(bb, bih_b, bhh_b, bf, bih_f, bhh_f);

    // precompute G[t][n][b] (fp16); grid (n-panels, m-panels): waves share A tiles
    lstm_gemm<<<dim3(NG / TN, BATCH * SEQ / TM), 256, GEMM_SMEM>>>(
        Xemb, EMB, Wib, bb, G, nullptr, 0, 0);

    // forward direction: single cell on last timestep, h=c=0 -> out[:, 0:2048]
    lstm_gemm<<<dim3(BATCH / TM, NG / TN), 256, GEMM_SMEM>>>(
        Xemb + (size_t)(SEQ - 1) * BATCH * EMB, EMB, Wif, bf, nullptr, out, 1, 2 * HID);

    // backward recurrence: one persistent kernel, 128 resident CTAs
    reset_cnt<<<1, 256>>>();
    lstm_recur<<<dim3(2, 64), 256, RECUR_SMEM>>>(
        G, Whh, H, H + (size_t)BATCH * HID, out);
}